// round 6
// baseline (speedup 1.0000x reference)
#include <cuda_runtime.h>

#define Fn 640
#define Vn 322
#define EPSf 1e-8f
#define HALF_BIGf 5e9f
#define FOCALf 3.73205080756887729f
#define NTILE 256            // 16x16 tiles of 16x16 pixels
#define NSEG 4               // co-blocks per tile (static face-id split)
#define SEGF 160             // faces per segment (640/4)

// -------- device-global scratch (zero-init at load; counters are monotonic,
//          g_seg/g_partial fully rewritten every replay -> graph-safe) --------
__device__ float4 g_seg[NSEG * 65536];      // {w0, w1, fid_bits, zbits}
__device__ int    g_tiledone[NTILE];        // monotonic, check (old & 3) == 3
__device__ double g_partial[NTILE];
__device__ unsigned int g_rcount;           // monotonic, check (old & 255) == 255

__global__ void __launch_bounds__(256) fused_kernel(const float* __restrict__ verts,
                                                    const int*   __restrict__ faces,
                                                    const float* __restrict__ tex,
                                                    const float* __restrict__ ref,
                                                    const float* __restrict__ angle,
                                                    float* __restrict__ out) {
    __shared__ float sx[Vn], sy[Vn], sd[Vn];
    __shared__ float4 sA[SEGF];             // w0x w0y w0c w1x
    __shared__ float4 sB[SEGF];             // w1y w1c zx  zy
    __shared__ float  sZc[SEGF];
    __shared__ unsigned short clist[SEGF];
    __shared__ int swcnt[5];
    __shared__ int sn;
    __shared__ double ss[8];
    __shared__ int sflag;

    int b = blockIdx.x, tid = threadIdx.x;
    int tile = b >> 2, seg = b & 3;
    int tx = tile & 15, ty = tile >> 4;

    // ---- vertex transform (all verts, redundant per block; cheap) ----
    float th = angle[0] * 6.28318530717958647692f;
    float c = cosf(th), s = sinf(th);
    for (int v = tid; v < Vn; v += 256) {
        float x = verts[3 * v], y = verts[3 * v + 1], z = verts[3 * v + 2];
        float xr = c * x + s * z;
        float zr = -s * x + c * z;
        float depth = 2.732f - zr;
        float invd = 1.0f / depth;                 // single divide
        sx[v] = FOCALf * xr * invd;
        sy[v] = FOCALf * y * invd;
        sd[v] = depth;
    }
    __syncthreads();

    // ---- plane compute + dilated-edge cull + compact (this seg's 160 faces) ----
    float cxt = (float)(tx * 16 + 8) / 128.0f - 1.0f;
    float cyt = 1.0f - (float)(ty * 16 + 8) / 128.0f;
    const float hext = 7.5f / 128.0f;

    bool pass = false;
    float4 A, B;
    float Zc = 0.f;
    int f = seg * SEGF + tid;
    if (tid < SEGF) {
        int i0 = faces[3 * f], i1 = faces[3 * f + 1], i2 = faces[3 * f + 2];
        float ax = sx[i0], ay = sy[i0];
        float bx = sx[i1], by = sy[i1];
        float cx = sx[i2], cy = sy[i2];
        float area = (bx - ax) * (cy - ay) - (by - ay) * (cx - ax);
        bool valid = fabsf(area) > EPSf;            // NaN -> invalid, matches jnp
        float inv = 1.0f / (valid ? area : 1.0f);   // single divide per face
        float e0x = cx - bx, e0y = cy - by;
        float w0x = -e0y * inv, w0y = e0x * inv, w0c = (e0y * bx - e0x * by) * inv;
        float e1x = ax - cx, e1y = ay - cy;
        float w1x = -e1y * inv, w1y = e1x * inv, w1c = (e1y * cx - e1x * cy) * inv;
        if (!valid) { w0x = 0.f; w0y = 0.f; w0c = -1e30f; w1x = 0.f; w1y = 0.f; w1c = 0.f; }
        float d0 = sd[i0], d1 = sd[i1], d2 = sd[i2];
        float e02 = d0 - d2, e12 = d1 - d2;
        float zx = w0x * e02 + w1x * e12;
        float zy = w0y * e02 + w1y * e12;
        float zc = d2 + w0c * e02 + w1c * e12;
        A = make_float4(w0x, w0y, w0c, w1x);
        B = make_float4(w1y, w1c, zx, zy);
        Zc = zc;
        // conservative tile cull (w2 plane derived locally, not stored)
        float w2x = -(w0x + w1x), w2y = -(w0y + w1y), w2c = 1.0f - w0c - w1c;
        float v0 = fmaf(w0x, cxt, fmaf(w0y, cyt, w0c));
        float m0 = (fabsf(w0x) + fabsf(w0y)) * hext
                 + 1e-5f * (fabsf(w0x) + fabsf(w0y) + fabsf(w0c));
        float v1 = fmaf(w1x, cxt, fmaf(w1y, cyt, w1c));
        float m1 = (fabsf(w1x) + fabsf(w1y)) * hext
                 + 1e-5f * (fabsf(w1x) + fabsf(w1y) + fabsf(w1c));
        float v2 = fmaf(w2x, cxt, fmaf(w2y, cyt, w2c));
        float m2 = (fabsf(w2x) + fabsf(w2y)) * hext
                 + 1e-5f * (fabsf(w2x) + fabsf(w2y) + fabsf(w2c));
        pass = (v0 + m0 >= 0.f) & (v1 + m1 >= 0.f) & (v2 + m2 >= 0.f);
    }
    unsigned mask = __ballot_sync(0xffffffffu, pass);
    int w = tid >> 5, lane = tid & 31;
    if (lane == 0 && w < 5) swcnt[w] = __popc(mask);
    __syncthreads();
    if (pass) {
        int off = __popc(mask & ((1u << lane) - 1u));
        for (int i = 0; i < w; i++) off += swcnt[i];   // warp order = face order
        sA[off] = A; sB[off] = B; sZc[off] = Zc;
        clist[off] = (unsigned short)f;
    }
    if (tid == 0) sn = swcnt[0] + swcnt[1] + swcnt[2] + swcnt[3] + swcnt[4];
    __syncthreads();
    int n = sn;

    // ---- raster: per-pixel min over this segment's culled faces ----
    int x = tx * 16 + (tid & 15);
    int y = ty * 16 + (tid >> 4);
    int p = y * 256 + x;
    float px = (x + 0.5f) / 128.0f - 1.0f;
    float py = 1.0f - (y + 0.5f) / 128.0f;

    float best = HALF_BIGf;                  // strict < == reference hit rule
    int jw = -1;
#pragma unroll 4
    for (int j = 0; j < n; j++) {
        float4 Aj = sA[j];
        float4 Bj = sB[j];
        float  zc = sZc[j];
        float w0 = fmaf(Aj.x, px, fmaf(Aj.y, py, Aj.z));
        float w1 = fmaf(Aj.w, px, fmaf(Bj.x, py, Bj.y));
        float z  = fmaf(Bj.z, px, fmaf(Bj.w, py, zc));
        float w2 = 1.0f - w0 - w1;           // exact reference formula
        float m  = fminf(fminf(w0, w1), w2);
        bool take = (m >= 0.f) & (z > EPSf) & (z < best);
        if (take) { best = z; jw = j; }      // ascending j == ascending f
    }
    float bw0 = 0.f, bw1 = 0.f;
    unsigned fid = 0;
    if (jw >= 0) {
        float4 Aj = sA[jw];
        float4 Bj = sB[jw];
        bw0 = fmaf(Aj.x, px, fmaf(Aj.y, py, Aj.z));
        bw1 = fmaf(Aj.w, px, fmaf(Bj.x, py, Bj.y));
        fid = (unsigned)clist[jw];
    }
    g_seg[(seg << 16) + p] =
        make_float4(bw0, bw1, __uint_as_float(fid), __uint_as_float(__float_as_uint(best)));
    __threadfence();                         // release this thread's segment slot
    __syncthreads();
    if (tid == 0) {
        int old = atomicAdd(&g_tiledone[tile], 1);
        sflag = ((old & 3) == 3);            // last co-block of the tile (mod-4: replay-safe)
    }
    __syncthreads();
    if (!sflag) return;

    // ---- epilogue: merge 4 segments, shade (tanh on the fly), loss ----
    unsigned long long bk = 0xFFFFFFFFFFFFFFFFull;
    float w0 = 0.f, w1 = 0.f;
#pragma unroll
    for (int sg = 0; sg < NSEG; sg++) {
        float4 v = __ldcg(&g_seg[(sg << 16) + p]);
        unsigned long long k =
            (((unsigned long long)__float_as_uint(v.w)) << 32) | __float_as_uint(v.z);
        if (k < bk) { bk = k; w0 = v.x; w1 = v.y; }   // (z, fid) lexicographic min
    }
    float col0 = 0.f, col1 = 0.f, col2 = 0.f;
    if ((unsigned)(bk >> 32) < __float_as_uint(HALF_BIGf)) {
        int fw = (int)(unsigned)(bk & 0xFFFFFFFFu);
        float pw[3] = { w0, w1, 1.0f - w0 - w1 };
        int   i0[3];
        float fr[3];
#pragma unroll
        for (int k = 0; k < 3; k++) {
            float u  = fminf(fmaxf(pw[k], 0.f), 1.f) * 3.0f;
            float fl = fminf(fmaxf(floorf(u), 0.f), 2.f);
            i0[k] = (int)fl;
            fr[k] = u - fl;
        }
        const float* tb = tex + fw * 192;
#pragma unroll
        for (int a = 0; a < 2; a++)
#pragma unroll
            for (int bb = 0; bb < 2; bb++)
#pragma unroll
                for (int cc = 0; cc < 2; cc++) {
                    float wc = (a  ? fr[0] : 1.f - fr[0])
                             * (bb ? fr[1] : 1.f - fr[1])
                             * (cc ? fr[2] : 1.f - fr[2]);
                    int idx = ((i0[0] + a) * 16 + (i0[1] + bb) * 4 + (i0[2] + cc)) * 3;
                    col0 += wc * tanhf(__ldg(tb + idx + 0));
                    col1 += wc * tanhf(__ldg(tb + idx + 1));
                    col2 += wc * tanhf(__ldg(tb + idx + 2));
                }
    }
    float d0 = col0 - ref[p];
    float d1 = col1 - ref[65536 + p];
    float d2 = col2 - ref[131072 + p];
    double sum = (double)d0 * d0 + (double)d1 * d1 + (double)d2 * d2;

#pragma unroll
    for (int o = 16; o; o >>= 1) sum += __shfl_down_sync(0xffffffffu, sum, o);
    if (lane == 0) ss[w] = sum;
    __syncthreads();
    if (tid == 0) {
        double t = 0.0;
        for (int i = 0; i < 8; i++) t += ss[i];
        g_partial[tile] = t;
        __threadfence();
        unsigned old = atomicAdd(&g_rcount, 1u);
        sflag = ((old & 255) == 255);        // very last tile (mod-256: replay-safe)
    }
    __syncthreads();
    if (sflag) {                             // fixed-order deterministic final reduce
        double v = __ldcg(&g_partial[tid]);
#pragma unroll
        for (int o = 16; o; o >>= 1) v += __shfl_down_sync(0xffffffffu, v, o);
        if (lane == 0) ss[w] = v;
        __syncthreads();
        if (tid == 0) {
            double t = 0.0;
            for (int i = 0; i < 8; i++) t += ss[i];
            out[0] = (float)t;
        }
    }
}

extern "C" void kernel_launch(void* const* d_in, const int* in_sizes, int n_in,
                              void* d_out, int out_size) {
    const float* verts = (const float*)d_in[0];   // (1,322,3)
    const int*   faces = (const int*)  d_in[1];   // (1,640,3)
    const float* tex   = (const float*)d_in[2];   // (1,640,4,4,4,3)
    const float* ref   = (const float*)d_in[3];   // (1,3,256,256)
    const float* angle = (const float*)d_in[4];   // (1,)

    fused_kernel<<<NTILE * NSEG, 256>>>(verts, faces, tex, ref, angle, (float*)d_out);
}

// round 7
// speedup vs baseline: 1.0120x; 1.0120x over previous
#include <cuda_runtime.h>

#define Fn 640
#define Vn 322
#define EPSf 1e-8f
#define HALF_BIGf 5e9f
#define FOCALf 3.73205080756887729f
#define NTILE 256            // 16x16 tiles of 16x16 pixels
#define NSEG 4               // co-blocks per tile (round-robin face split)
#define SEGF 160             // faces per segment (640/4)

// -------- device-global scratch (zero-init at load; counters are monotonic,
//          g_seg/g_partial fully rewritten every replay -> graph-safe) --------
__device__ float4 g_seg[NSEG * 65536];      // {w0, w1, fid_bits, zbits}
__device__ int    g_tiledone[NTILE];        // monotonic, check (old & 3) == 3
__device__ double g_partial[NTILE];
__device__ unsigned int g_rcount;           // monotonic, check (old & 255) == 255

__device__ __forceinline__ float tanh_mufu(float x) {
    float y;
    asm("tanh.approx.f32 %0, %1;" : "=f"(y) : "f"(x));
    return y;
}

__global__ void __launch_bounds__(256) fused_kernel(const float* __restrict__ verts,
                                                    const int*   __restrict__ faces,
                                                    const float* __restrict__ tex,
                                                    const float* __restrict__ ref,
                                                    const float* __restrict__ angle,
                                                    float* __restrict__ out) {
    __shared__ float sx[Vn], sy[Vn], sd[Vn];
    __shared__ float4 sA[SEGF];             // w0x w0y w0c w1x
    __shared__ float4 sB[SEGF];             // w1y w1c zx  zy
    __shared__ float  sZc[SEGF];
    __shared__ unsigned short clist[SEGF];
    __shared__ int swcnt[5];
    __shared__ int sn;
    __shared__ double ss[8];
    __shared__ int sflag;

    int b = blockIdx.x, tid = threadIdx.x;
    int tile = b >> 2, seg = b & 3;
    int tx = tile & 15, ty = tile >> 4;

    // ---- vertex transform (all verts, redundant per block; cheap) ----
    float th = angle[0] * 6.28318530717958647692f;
    float c = cosf(th), s = sinf(th);
    for (int v = tid; v < Vn; v += 256) {
        float x = verts[3 * v], y = verts[3 * v + 1], z = verts[3 * v + 2];
        float xr = c * x + s * z;
        float zr = -s * x + c * z;
        float depth = 2.732f - zr;
        float invd = 1.0f / depth;
        sx[v] = FOCALf * xr * invd;
        sy[v] = FOCALf * y * invd;
        sd[v] = depth;
    }
    __syncthreads();

    // ---- plane compute + dilated-edge cull + compact (round-robin faces) ----
    float cxt = (float)(tx * 16 + 8) / 128.0f - 1.0f;
    float cyt = 1.0f - (float)(ty * 16 + 8) / 128.0f;
    const float hext = 7.5f / 128.0f;

    bool pass = false;
    float4 A, B;
    float Zc = 0.f;
    int f = 4 * tid + seg;                   // round-robin: balances seg straggler
    if (tid < SEGF) {
        int i0 = faces[3 * f], i1 = faces[3 * f + 1], i2 = faces[3 * f + 2];
        float ax = sx[i0], ay = sy[i0];
        float bx = sx[i1], by = sy[i1];
        float cx = sx[i2], cy = sy[i2];
        float area = (bx - ax) * (cy - ay) - (by - ay) * (cx - ax);
        bool valid = fabsf(area) > EPSf;            // NaN -> invalid, matches jnp
        float inv = 1.0f / (valid ? area : 1.0f);
        float e0x = cx - bx, e0y = cy - by;
        float w0x = -e0y * inv, w0y = e0x * inv, w0c = (e0y * bx - e0x * by) * inv;
        float e1x = ax - cx, e1y = ay - cy;
        float w1x = -e1y * inv, w1y = e1x * inv, w1c = (e1y * cx - e1x * cy) * inv;
        if (!valid) { w0x = 0.f; w0y = 0.f; w0c = -1e30f; w1x = 0.f; w1y = 0.f; w1c = 0.f; }
        float d0 = sd[i0], d1 = sd[i1], d2 = sd[i2];
        float e02 = d0 - d2, e12 = d1 - d2;
        float zx = w0x * e02 + w1x * e12;
        float zy = w0y * e02 + w1y * e12;
        float zc = d2 + w0c * e02 + w1c * e12;
        A = make_float4(w0x, w0y, w0c, w1x);
        B = make_float4(w1y, w1c, zx, zy);
        Zc = zc;
        float w2x = -(w0x + w1x), w2y = -(w0y + w1y), w2c = 1.0f - w0c - w1c;
        float v0 = fmaf(w0x, cxt, fmaf(w0y, cyt, w0c));
        float m0 = (fabsf(w0x) + fabsf(w0y)) * hext
                 + 1e-5f * (fabsf(w0x) + fabsf(w0y) + fabsf(w0c));
        float v1 = fmaf(w1x, cxt, fmaf(w1y, cyt, w1c));
        float m1 = (fabsf(w1x) + fabsf(w1y)) * hext
                 + 1e-5f * (fabsf(w1x) + fabsf(w1y) + fabsf(w1c));
        float v2 = fmaf(w2x, cxt, fmaf(w2y, cyt, w2c));
        float m2 = (fabsf(w2x) + fabsf(w2y)) * hext
                 + 1e-5f * (fabsf(w2x) + fabsf(w2y) + fabsf(w2c));
        pass = (v0 + m0 >= 0.f) & (v1 + m1 >= 0.f) & (v2 + m2 >= 0.f);
    }
    unsigned mask = __ballot_sync(0xffffffffu, pass);
    int w = tid >> 5, lane = tid & 31;
    if (lane == 0 && w < 5) swcnt[w] = __popc(mask);
    __syncthreads();
    if (pass) {
        int off = __popc(mask & ((1u << lane) - 1u));
        for (int i = 0; i < w; i++) off += swcnt[i];   // warp order = ascending f
        sA[off] = A; sB[off] = B; sZc[off] = Zc;
        clist[off] = (unsigned short)f;
    }
    if (tid == 0) sn = swcnt[0] + swcnt[1] + swcnt[2] + swcnt[3] + swcnt[4];
    __syncthreads();
    int n = sn;

    // ---- raster: per-pixel min over this segment's culled faces ----
    int x = tx * 16 + (tid & 15);
    int y = ty * 16 + (tid >> 4);
    int p = y * 256 + x;
    float px = (x + 0.5f) / 128.0f - 1.0f;
    float py = 1.0f - (y + 0.5f) / 128.0f;

    float best = HALF_BIGf;                  // strict < == reference hit rule
    int jw = -1;
#pragma unroll 4
    for (int j = 0; j < n; j++) {
        float4 Aj = sA[j];
        float4 Bj = sB[j];
        float  zc = sZc[j];
        float w0 = fmaf(Aj.x, px, fmaf(Aj.y, py, Aj.z));
        float w1 = fmaf(Aj.w, px, fmaf(Bj.x, py, Bj.y));
        float z  = fmaf(Bj.z, px, fmaf(Bj.w, py, zc));
        float w2 = 1.0f - w0 - w1;           // exact reference formula
        float m  = fminf(fminf(w0, w1), w2);
        bool take = (m >= 0.f) & (z > EPSf) & (z < best);
        if (take) { best = z; jw = j; }
    }
    float bw0 = 0.f, bw1 = 0.f;
    unsigned fid = 0;
    if (jw >= 0) {
        float4 Aj = sA[jw];
        float4 Bj = sB[jw];
        bw0 = fmaf(Aj.x, px, fmaf(Aj.y, py, Aj.z));
        bw1 = fmaf(Aj.w, px, fmaf(Bj.x, py, Bj.y));
        fid = (unsigned)clist[jw];
    }
    g_seg[(seg << 16) + p] =
        make_float4(bw0, bw1, __uint_as_float(fid), __uint_as_float(__float_as_uint(best)));
    __syncthreads();                         // orders all block's writes before tid0's fence
    if (tid == 0) {
        __threadfence();                     // single release fence for the whole block
        int old = atomicAdd(&g_tiledone[tile], 1);
        sflag = ((old & 3) == 3);            // last co-block of the tile (mod-4: replay-safe)
        if (sflag) __threadfence();          // acquire: see peer blocks' g_seg writes
    }
    __syncthreads();
    if (!sflag) return;

    // ---- epilogue: merge 4 segments, shade (MUFU tanh), loss ----
    unsigned long long bk = 0xFFFFFFFFFFFFFFFFull;
    float w0 = 0.f, w1 = 0.f;
#pragma unroll
    for (int sg = 0; sg < NSEG; sg++) {
        float4 v = __ldcg(&g_seg[(sg << 16) + p]);
        unsigned long long k =
            (((unsigned long long)__float_as_uint(v.w)) << 32) | __float_as_uint(v.z);
        if (k < bk) { bk = k; w0 = v.x; w1 = v.y; }   // (z, fid) lexicographic min
    }
    float col0 = 0.f, col1 = 0.f, col2 = 0.f;
    if ((unsigned)(bk >> 32) < __float_as_uint(HALF_BIGf)) {
        int fw = (int)(unsigned)(bk & 0xFFFFFFFFu);
        float pw[3] = { w0, w1, 1.0f - w0 - w1 };
        int   i0[3];
        float fr[3];
#pragma unroll
        for (int k = 0; k < 3; k++) {
            float u  = fminf(fmaxf(pw[k], 0.f), 1.f) * 3.0f;
            float fl = fminf(fmaxf(floorf(u), 0.f), 2.f);
            i0[k] = (int)fl;
            fr[k] = u - fl;
        }
        const float* tb = tex + fw * 192;
#pragma unroll
        for (int a = 0; a < 2; a++)
#pragma unroll
            for (int bb = 0; bb < 2; bb++)
#pragma unroll
                for (int cc = 0; cc < 2; cc++) {
                    float wc = (a  ? fr[0] : 1.f - fr[0])
                             * (bb ? fr[1] : 1.f - fr[1])
                             * (cc ? fr[2] : 1.f - fr[2]);
                    int idx = ((i0[0] + a) * 16 + (i0[1] + bb) * 4 + (i0[2] + cc)) * 3;
                    col0 += wc * tanh_mufu(__ldg(tb + idx + 0));
                    col1 += wc * tanh_mufu(__ldg(tb + idx + 1));
                    col2 += wc * tanh_mufu(__ldg(tb + idx + 2));
                }
    }
    float d0 = col0 - ref[p];
    float d1 = col1 - ref[65536 + p];
    float d2 = col2 - ref[131072 + p];
    double sum = (double)d0 * d0 + (double)d1 * d1 + (double)d2 * d2;

#pragma unroll
    for (int o = 16; o; o >>= 1) sum += __shfl_down_sync(0xffffffffu, sum, o);
    if (lane == 0) ss[w] = sum;
    __syncthreads();
    if (tid == 0) {
        double t = 0.0;
        for (int i = 0; i < 8; i++) t += ss[i];
        g_partial[tile] = t;
        __threadfence();                     // release g_partial
        unsigned old = atomicAdd(&g_rcount, 1u);
        sflag = ((old & 255) == 255);        // very last tile (mod-256: replay-safe)
        if (sflag) __threadfence();          // acquire
    }
    __syncthreads();
    if (sflag) {                             // fixed-order deterministic final reduce
        double v = __ldcg(&g_partial[tid]);
#pragma unroll
        for (int o = 16; o; o >>= 1) v += __shfl_down_sync(0xffffffffu, v, o);
        if (lane == 0) ss[w] = v;
        __syncthreads();
        if (tid == 0) {
            double t = 0.0;
            for (int i = 0; i < 8; i++) t += ss[i];
            out[0] = (float)t;
        }
    }
}

extern "C" void kernel_launch(void* const* d_in, const int* in_sizes, int n_in,
                              void* d_out, int out_size) {
    const float* verts = (const float*)d_in[0];   // (1,322,3)
    const int*   faces = (const int*)  d_in[1];   // (1,640,3)
    const float* tex   = (const float*)d_in[2];   // (1,640,4,4,4,3)
    const float* ref   = (const float*)d_in[3];   // (1,3,256,256)
    const float* angle = (const float*)d_in[4];   // (1,)

    fused_kernel<<<NTILE * NSEG, 256>>>(verts, faces, tex, ref, angle, (float*)d_out);
}

// round 8
// speedup vs baseline: 1.1368x; 1.1233x over previous
#include <cuda_runtime.h>

#define Fn 640
#define Vn 322
#define EPSf 1e-8f
#define HALF_BIGf 5e9f
#define FOCALf 3.73205080756887729f
#define NTILE 256            // 16x16 tiles of 16x16 pixels
#define NSEG 4               // co-blocks per tile (round-robin face split)
#define SEGF 160             // faces per segment (640/4)

// -------- device-global scratch (zero-init at load; counters are monotonic,
//          g_seg/g_partial fully rewritten every replay -> graph-safe) --------
__device__ float4 g_seg[NSEG * 65536];      // {w0, w1, fid_bits, zbits}
__device__ int    g_tiledone[NTILE];        // monotonic, check (old & 3) == 3
__device__ double g_partial[NTILE];
__device__ unsigned int g_rcount;           // monotonic, check (old & 255) == 255

__device__ __forceinline__ float tanh_mufu(float x) {
    float y;
    asm("tanh.approx.f32 %0, %1;" : "=f"(y) : "f"(x));
    return y;
}

__global__ void __launch_bounds__(256) fused_kernel(const float* __restrict__ verts,
                                                    const int*   __restrict__ faces,
                                                    const float* __restrict__ tex,
                                                    const float* __restrict__ ref,
                                                    const float* __restrict__ angle,
                                                    float* __restrict__ out) {
    __shared__ float sx[Vn], sy[Vn], sd[Vn];
    __shared__ float4 sA[SEGF];             // w0x w0y w0c w1x
    __shared__ float4 sB[SEGF];             // w1y w1c zx  zy
    __shared__ float  sZc[SEGF];
    __shared__ unsigned short clist[SEGF];
    __shared__ int swcnt[5];
    __shared__ int sn;
    __shared__ double ss[8];
    __shared__ int sflag;

    int b = blockIdx.x, tid = threadIdx.x;
    int tile = b >> 2, seg = b & 3;
    int tx = tile & 15, ty = tile >> 4;

    // ---- vertex transform (all verts, redundant per block; MUFU sincos) ----
    float th = angle[0] * 6.28318530717958647692f;
    float c = __cosf(th), s = __sinf(th);
    for (int v = tid; v < Vn; v += 256) {
        float x = verts[3 * v], y = verts[3 * v + 1], z = verts[3 * v + 2];
        float xr = c * x + s * z;
        float zr = -s * x + c * z;
        float depth = 2.732f - zr;
        float invd = 1.0f / depth;
        sx[v] = FOCALf * xr * invd;
        sy[v] = FOCALf * y * invd;
        sd[v] = depth;
    }
    __syncthreads();

    // ---- plane compute + full SAT cull (3 edges + bbox axes) + compact ----
    float cxt = (float)(tx * 16 + 8) / 128.0f - 1.0f;
    float cyt = 1.0f - (float)(ty * 16 + 8) / 128.0f;
    const float hext = 7.5f / 128.0f;
    // tile pixel-center bounding box
    float txmin = (float)(tx * 16) / 128.0f + 0.5f / 128.0f - 1.0f;
    float txmax = txmin + 15.0f / 128.0f;
    float tymax = 1.0f - ((float)(ty * 16) / 128.0f + 0.5f / 128.0f);
    float tymin = tymax - 15.0f / 128.0f;

    bool pass = false;
    float4 A, B;
    float Zc = 0.f;
    int f = 4 * tid + seg;                   // round-robin: balances seg straggler
    if (tid < SEGF) {
        int i0 = faces[3 * f], i1 = faces[3 * f + 1], i2 = faces[3 * f + 2];
        float ax = sx[i0], ay = sy[i0];
        float bx = sx[i1], by = sy[i1];
        float cx = sx[i2], cy = sy[i2];
        float area = (bx - ax) * (cy - ay) - (by - ay) * (cx - ax);
        bool valid = fabsf(area) > EPSf;            // NaN -> invalid, matches jnp
        float inv = 1.0f / (valid ? area : 1.0f);
        float e0x = cx - bx, e0y = cy - by;
        float w0x = -e0y * inv, w0y = e0x * inv, w0c = (e0y * bx - e0x * by) * inv;
        float e1x = ax - cx, e1y = ay - cy;
        float w1x = -e1y * inv, w1y = e1x * inv, w1c = (e1y * cx - e1x * cy) * inv;
        if (!valid) { w0x = 0.f; w0y = 0.f; w0c = -1e30f; w1x = 0.f; w1y = 0.f; w1c = 0.f; }
        float d0 = sd[i0], d1 = sd[i1], d2 = sd[i2];
        float e02 = d0 - d2, e12 = d1 - d2;
        float zx = w0x * e02 + w1x * e12;
        float zy = w0y * e02 + w1y * e12;
        float zc = d2 + w0c * e02 + w1c * e12;
        A = make_float4(w0x, w0y, w0c, w1x);
        B = make_float4(w1y, w1c, zx, zy);
        Zc = zc;
        // (1) dilated edge half-planes
        float w2x = -(w0x + w1x), w2y = -(w0y + w1y), w2c = 1.0f - w0c - w1c;
        float v0 = fmaf(w0x, cxt, fmaf(w0y, cyt, w0c));
        float m0 = (fabsf(w0x) + fabsf(w0y)) * hext
                 + 1e-5f * (fabsf(w0x) + fabsf(w0y) + fabsf(w0c));
        float v1 = fmaf(w1x, cxt, fmaf(w1y, cyt, w1c));
        float m1 = (fabsf(w1x) + fabsf(w1y)) * hext
                 + 1e-5f * (fabsf(w1x) + fabsf(w1y) + fabsf(w1c));
        float v2 = fmaf(w2x, cxt, fmaf(w2y, cyt, w2c));
        float m2 = (fabsf(w2x) + fabsf(w2y)) * hext
                 + 1e-5f * (fabsf(w2x) + fabsf(w2y) + fabsf(w2c));
        pass = (v0 + m0 >= 0.f) & (v1 + m1 >= 0.f) & (v2 + m2 >= 0.f);
        // (2) bbox axes (caps miter spikes of skinny triangles).
        //     Any pixel center inside the triangle lies inside the tri bbox,
        //     so overlap (with margin >> ulp) is a sound necessary condition.
        float bxmin = fminf(ax, fminf(bx, cx)), bxmax = fmaxf(ax, fmaxf(bx, cx));
        float bymin = fminf(ay, fminf(by, cy)), bymax = fmaxf(ay, fmaxf(by, cy));
        pass = pass & (bxmax >= txmin - 1e-4f) & (bxmin <= txmax + 1e-4f)
                    & (bymax >= tymin - 1e-4f) & (bymin <= tymax + 1e-4f);
    }
    unsigned mask = __ballot_sync(0xffffffffu, pass);
    int w = tid >> 5, lane = tid & 31;
    if (lane == 0 && w < 5) swcnt[w] = __popc(mask);
    __syncthreads();
    if (pass) {
        int off = __popc(mask & ((1u << lane) - 1u));
        for (int i = 0; i < w; i++) off += swcnt[i];   // warp order = ascending f
        sA[off] = A; sB[off] = B; sZc[off] = Zc;
        clist[off] = (unsigned short)f;
    }
    if (tid == 0) sn = swcnt[0] + swcnt[1] + swcnt[2] + swcnt[3] + swcnt[4];
    __syncthreads();
    int n = sn;

    // ---- raster: per-pixel min over this segment's culled faces ----
    int x = tx * 16 + (tid & 15);
    int y = ty * 16 + (tid >> 4);
    int p = y * 256 + x;
    float px = (x + 0.5f) / 128.0f - 1.0f;
    float py = 1.0f - (y + 0.5f) / 128.0f;

    float best = HALF_BIGf;                  // strict < == reference hit rule
    int jw = -1;
#pragma unroll 4
    for (int j = 0; j < n; j++) {
        float4 Aj = sA[j];
        float4 Bj = sB[j];
        float  zc = sZc[j];
        float w0 = fmaf(Aj.x, px, fmaf(Aj.y, py, Aj.z));
        float w1 = fmaf(Aj.w, px, fmaf(Bj.x, py, Bj.y));
        float z  = fmaf(Bj.z, px, fmaf(Bj.w, py, zc));
        float w2 = 1.0f - w0 - w1;           // exact reference formula
        float m  = fminf(fminf(w0, w1), w2);
        bool take = (m >= 0.f) & (z > EPSf) & (z < best);
        if (take) { best = z; jw = j; }
    }
    float bw0 = 0.f, bw1 = 0.f;
    unsigned fid = 0;
    if (jw >= 0) {
        float4 Aj = sA[jw];
        float4 Bj = sB[jw];
        bw0 = fmaf(Aj.x, px, fmaf(Aj.y, py, Aj.z));
        bw1 = fmaf(Aj.w, px, fmaf(Bj.x, py, Bj.y));
        fid = (unsigned)clist[jw];
    }
    g_seg[(seg << 16) + p] =
        make_float4(bw0, bw1, __uint_as_float(fid), __uint_as_float(__float_as_uint(best)));
    __syncthreads();                         // orders all block's writes before tid0's fence
    if (tid == 0) {
        __threadfence();                     // single release fence for the whole block
        int old = atomicAdd(&g_tiledone[tile], 1);
        sflag = ((old & 3) == 3);            // last co-block of the tile (mod-4: replay-safe)
        if (sflag) __threadfence();          // acquire: see peer blocks' g_seg writes
    }
    __syncthreads();
    if (!sflag) return;

    // ---- epilogue: merge 4 segments, shade (MUFU tanh), loss ----
    unsigned long long bk = 0xFFFFFFFFFFFFFFFFull;
    float w0 = 0.f, w1 = 0.f;
#pragma unroll
    for (int sg = 0; sg < NSEG; sg++) {
        float4 v = __ldcg(&g_seg[(sg << 16) + p]);
        unsigned long long k =
            (((unsigned long long)__float_as_uint(v.w)) << 32) | __float_as_uint(v.z);
        if (k < bk) { bk = k; w0 = v.x; w1 = v.y; }   // (z, fid) lexicographic min
    }
    float col0 = 0.f, col1 = 0.f, col2 = 0.f;
    if ((unsigned)(bk >> 32) < __float_as_uint(HALF_BIGf)) {
        int fw = (int)(unsigned)(bk & 0xFFFFFFFFu);
        float pw[3] = { w0, w1, 1.0f - w0 - w1 };
        int   i0[3];
        float fr[3];
#pragma unroll
        for (int k = 0; k < 3; k++) {
            float u  = fminf(fmaxf(pw[k], 0.f), 1.f) * 3.0f;
            float fl = fminf(fmaxf(floorf(u), 0.f), 2.f);
            i0[k] = (int)fl;
            fr[k] = u - fl;
        }
        const float* tb = tex + fw * 192;
#pragma unroll
        for (int a = 0; a < 2; a++)
#pragma unroll
            for (int bb = 0; bb < 2; bb++)
#pragma unroll
                for (int cc = 0; cc < 2; cc++) {
                    float wc = (a  ? fr[0] : 1.f - fr[0])
                             * (bb ? fr[1] : 1.f - fr[1])
                             * (cc ? fr[2] : 1.f - fr[2]);
                    int idx = ((i0[0] + a) * 16 + (i0[1] + bb) * 4 + (i0[2] + cc)) * 3;
                    col0 += wc * tanh_mufu(__ldg(tb + idx + 0));
                    col1 += wc * tanh_mufu(__ldg(tb + idx + 1));
                    col2 += wc * tanh_mufu(__ldg(tb + idx + 2));
                }
    }
    float d0 = col0 - ref[p];
    float d1 = col1 - ref[65536 + p];
    float d2 = col2 - ref[131072 + p];
    double sum = (double)d0 * d0 + (double)d1 * d1 + (double)d2 * d2;

#pragma unroll
    for (int o = 16; o; o >>= 1) sum += __shfl_down_sync(0xffffffffu, sum, o);
    if (lane == 0) ss[w] = sum;
    __syncthreads();
    if (tid == 0) {
        double t = 0.0;
        for (int i = 0; i < 8; i++) t += ss[i];
        g_partial[tile] = t;
        __threadfence();                     // release g_partial
        unsigned old = atomicAdd(&g_rcount, 1u);
        sflag = ((old & 255) == 255);        // very last tile (mod-256: replay-safe)
        if (sflag) __threadfence();          // acquire
    }
    __syncthreads();
    if (sflag) {                             // fixed-order deterministic final reduce
        double v = __ldcg(&g_partial[tid]);
#pragma unroll
        for (int o = 16; o; o >>= 1) v += __shfl_down_sync(0xffffffffu, v, o);
        if (lane == 0) ss[w] = v;
        __syncthreads();
        if (tid == 0) {
            double t = 0.0;
            for (int i = 0; i < 8; i++) t += ss[i];
            out[0] = (float)t;
        }
    }
}

extern "C" void kernel_launch(void* const* d_in, const int* in_sizes, int n_in,
                              void* d_out, int out_size) {
    const float* verts = (const float*)d_in[0];   // (1,322,3)
    const int*   faces = (const int*)  d_in[1];   // (1,640,3)
    const float* tex   = (const float*)d_in[2];   // (1,640,4,4,4,3)
    const float* ref   = (const float*)d_in[3];   // (1,3,256,256)
    const float* angle = (const float*)d_in[4];   // (1,)

    fused_kernel<<<NTILE * NSEG, 256>>>(verts, faces, tex, ref, angle, (float*)d_out);
}